// round 12
// baseline (speedup 1.0000x reference)
#include <cuda_runtime.h>
#include <cuda_bf16.h>
#include <cstdint>
#include <math.h>

// CapacityAwareRouter: x(8192,2048) @ W(64,2048)^T + bias -> greedy capacity routing
#define N_TOK   8192
#define N_EXP   64
#define DIM     2048
#define TOPK    4
#define OUT_W_OFF (N_TOK * TOPK)
#define CAND_MAX 8
#define MARGIN  0.06f

// GEMM: 256 blocks = 64 token-tiles x 4 K-quarters; 256 threads (8 warps of 32x32)
#define MT      128
#define NTILE   (N_TOK / MT)     // 64
#define NKQ     4
#define KQ      (DIM / NKQ)      // 512
#define KC      32               // K elems per chunk
#define NCHUNK  (KQ / KC)        // 16
#define XSTR    80               // bytes per smem row (64 data + 16 pad)
#define WSTR    80
#define XBYTES  (MT * XSTR)      // 10240
#define WBYTES  (N_EXP * WSTR)   // 5120

// ---------------- device scratch ----------------
__device__ __align__(16) float g_part[NKQ * N_TOK * N_EXP];  // 8 MB partial logits
__device__ int   g_count[N_EXP];
__device__ int   g_done;
__device__ __align__(16) __nv_bfloat16 g_wbf[N_EXP * DIM];   // 256 KB bf16 W

__device__ __forceinline__ uint32_t bf2(float lo, float hi) {
    uint32_t r;
    asm("cvt.rn.bf16x2.f32 %0, %2, %1;" : "=r"(r) : "f"(lo), "f"(hi));
    return r;
}
#define CP16(dst, src) \
    asm volatile("cp.async.cg.shared.global [%0], [%1], 16;" :: "r"(dst), "l"(src) : "memory")
#define CP_COMMIT() asm volatile("cp.async.commit_group;" ::: "memory")
#define CP_WAIT0()  asm volatile("cp.async.wait_group 0;" ::: "memory")

__device__ __forceinline__ void mma16816(float* c, uint32_t a0, uint32_t a1,
                                         uint32_t a2, uint32_t a3,
                                         uint32_t b0, uint32_t b1) {
    asm volatile(
        "mma.sync.aligned.m16n8k16.row.col.f32.bf16.bf16.f32 "
        "{%0,%1,%2,%3}, {%4,%5,%6,%7}, {%8,%9}, {%0,%1,%2,%3};"
        : "+f"(c[0]), "+f"(c[1]), "+f"(c[2]), "+f"(c[3])
        : "r"(a0), "r"(a1), "r"(a2), "r"(a3), "r"(b0), "r"(b1));
}

// ============ kernel 1: fp32 W -> bf16 global ============
__global__ void wconv_kernel(const float* __restrict__ W) {
    const int i = (blockIdx.x * 256 + threadIdx.x) * 8;
    float4 a = *(const float4*)(W + i);
    float4 b = *(const float4*)(W + i + 4);
    uint4 v;
    v.x = bf2(a.x, a.y); v.y = bf2(a.z, a.w);
    v.z = bf2(b.x, b.y); v.w = bf2(b.z, b.w);
    *(uint4*)(g_wbf + i) = v;
}

// ============ kernel 2: split-K bf16 MMA GEMM -> partial logits ============
__global__ __launch_bounds__(256, 2)
void gemm_kernel(const float* __restrict__ x) {
    __shared__ __align__(16) char smx[2 * XBYTES];   // 20480
    __shared__ __align__(16) char smw[2 * WBYTES];   // 10240

    const int tid  = threadIdx.x;
    const int wid  = tid >> 5;
    const int lane = tid & 31;
    const int tile = blockIdx.x & (NTILE - 1);
    const int kq   = blockIdx.x >> 6;
    const int m0   = tile * MT;
    const int k0   = kq * KQ;

    // x loader: 2 thr/row, 16 floats each (covers KC=32)
    const int xrow = tid >> 1;
    const int xh   = tid & 1;
    const float4* xp = (const float4*)(x + (size_t)(m0 + xrow) * DIM + k0 + xh * 16);
    // W loader: 4 thr/row, 8 bf16 (16B) each via cp.async
    const int wrow = tid >> 2;
    const __nv_bfloat16* wsrc = g_wbf + (size_t)wrow * DIM + k0 + (tid & 3) * 8;
    const uint32_t smw_base = (uint32_t)__cvta_generic_to_shared(smw);
    const uint32_t smx_base = (uint32_t)__cvta_generic_to_shared(smx);
    const uint32_t wdst = smw_base + (uint32_t)(wrow * WSTR + (tid & 3) * 16);

    // warp tile: 32 tokens x 32 experts
    const int wm = wid >> 1;             // 0..3 token group
    const int wn = wid & 1;              // 0..1 expert group
    const int qr = lane >> 2, qc = lane & 3;
    const uint32_t a_off = (uint32_t)((wm * 32 + (lane & 15)) * XSTR + (lane >> 4) * 16);
    const uint32_t b_off = (uint32_t)((wn * 32 + ((lane >> 4) << 3) + (lane & 7)) * WSTR
                                      + ((lane >> 3) & 1) * 16);

    float c[2][4][4];
    #pragma unroll
    for (int rg = 0; rg < 2; rg++)
        #pragma unroll
        for (int cg = 0; cg < 4; cg++)
            #pragma unroll
            for (int i = 0; i < 4; i++) c[rg][cg][i] = 0.f;

    // prologue: x chunks 0,1 in regs; W chunk 0 via cp.async (R8-proven 2-buffer)
    float4 rx[2][4];
    #pragma unroll
    for (int i = 0; i < 4; i++) rx[0][i] = xp[i];
    xp += KC / 4;
    #pragma unroll
    for (int i = 0; i < 4; i++) rx[1][i] = xp[i];
    xp += KC / 4;
    CP16(wdst, wsrc); CP_COMMIT(); wsrc += KC;

    for (int ci = 0; ci < NCHUNK; ci++) {
        const int buf = ci & 1;
        // STS x(ci): 16 fp32 -> 8 bf16x2 -> two STS.128
        {
            uint4 v0, v1;
            v0.x = bf2(rx[buf][0].x, rx[buf][0].y);
            v0.y = bf2(rx[buf][0].z, rx[buf][0].w);
            v0.z = bf2(rx[buf][1].x, rx[buf][1].y);
            v0.w = bf2(rx[buf][1].z, rx[buf][1].w);
            v1.x = bf2(rx[buf][2].x, rx[buf][2].y);
            v1.y = bf2(rx[buf][2].z, rx[buf][2].w);
            v1.z = bf2(rx[buf][3].x, rx[buf][3].y);
            v1.w = bf2(rx[buf][3].z, rx[buf][3].w);
            char* d = smx + buf * XBYTES + xrow * XSTR + xh * 32;
            *(uint4*)d = v0;
            *(uint4*)(d + 16) = v1;
        }
        if (ci + 2 < NCHUNK) {
            #pragma unroll
            for (int i = 0; i < 4; i++) rx[buf][i] = xp[i];
            xp += KC / 4;
        }
        CP_WAIT0();            // W(ci) landed
        __syncthreads();       // x(ci)/W(ci) visible; compute(ci-1) drained
        if (ci + 1 < NCHUNK) { // W(ci+1) into buffer freed by compute(ci-1)
            CP16(wdst + (buf ^ 1) * WBYTES, wsrc); CP_COMMIT(); wsrc += KC;
        }

        const uint32_t abase = smx_base + buf * XBYTES + a_off;
        const uint32_t bbase = smw_base + buf * WBYTES + b_off;
        #pragma unroll
        for (int kk = 0; kk < 2; kk++) {
            uint32_t A0[4], A1[4], B0[4], B1[4];
            asm volatile("ldmatrix.sync.aligned.m8n8.x4.shared.b16 {%0,%1,%2,%3}, [%4];"
                         : "=r"(A0[0]), "=r"(A0[1]), "=r"(A0[2]), "=r"(A0[3])
                         : "r"(abase + kk * 32));
            asm volatile("ldmatrix.sync.aligned.m8n8.x4.shared.b16 {%0,%1,%2,%3}, [%4];"
                         : "=r"(A1[0]), "=r"(A1[1]), "=r"(A1[2]), "=r"(A1[3])
                         : "r"(abase + 16 * XSTR + kk * 32));
            asm volatile("ldmatrix.sync.aligned.m8n8.x4.shared.b16 {%0,%1,%2,%3}, [%4];"
                         : "=r"(B0[0]), "=r"(B0[1]), "=r"(B0[2]), "=r"(B0[3])
                         : "r"(bbase + kk * 32));
            asm volatile("ldmatrix.sync.aligned.m8n8.x4.shared.b16 {%0,%1,%2,%3}, [%4];"
                         : "=r"(B1[0]), "=r"(B1[1]), "=r"(B1[2]), "=r"(B1[3])
                         : "r"(bbase + 16 * WSTR + kk * 32));
            mma16816(c[0][0], A0[0], A0[1], A0[2], A0[3], B0[0], B0[1]);
            mma16816(c[0][1], A0[0], A0[1], A0[2], A0[3], B0[2], B0[3]);
            mma16816(c[0][2], A0[0], A0[1], A0[2], A0[3], B1[0], B1[1]);
            mma16816(c[0][3], A0[0], A0[1], A0[2], A0[3], B1[2], B1[3]);
            mma16816(c[1][0], A1[0], A1[1], A1[2], A1[3], B0[0], B0[1]);
            mma16816(c[1][1], A1[0], A1[1], A1[2], A1[3], B0[2], B0[3]);
            mma16816(c[1][2], A1[0], A1[1], A1[2], A1[3], B1[0], B1[1]);
            mma16816(c[1][3], A1[0], A1[1], A1[2], A1[3], B1[2], B1[3]);
        }
    }

    // direct epilogue: fragment -> g_part (no smem staging)
    {
        float* base = &g_part[(size_t)kq * N_TOK * N_EXP + (size_t)m0 * N_EXP];
        #pragma unroll
        for (int rg = 0; rg < 2; rg++)
            #pragma unroll
            for (int cg = 0; cg < 4; cg++) {
                const int row = wm * 32 + rg * 16 + qr;
                const int col = wn * 32 + cg * 8 + qc * 2;
                float2 v0 = make_float2(c[rg][cg][0], c[rg][cg][1]);
                float2 v1 = make_float2(c[rg][cg][2], c[rg][cg][3]);
                *(float2*)&base[(size_t)row * N_EXP + col]       = v0;
                *(float2*)&base[(size_t)(row + 8) * N_EXP + col] = v1;
            }
    }
}

// ============ kernel 3: reduce partials + route + fallback spinner ============
__global__ __launch_bounds__(256, 2)
void route_kernel(const float* __restrict__ x, const float* __restrict__ Wt,
                  const float* __restrict__ bias, const int* __restrict__ tc,
                  float* __restrict__ out) {
    __shared__ float s_bias[N_EXP];
    __shared__ int   s_cnt[N_EXP];
    __shared__ int   s_queue[MT];
    __shared__ int   s_nc[MT];
    __shared__ int   s_cand[MT][CAND_MAX];
    __shared__ int   s_qn;
    __shared__ int   s_bad;

    const int tid  = threadIdx.x;
    const int wid  = tid >> 5;
    const int lane = tid & 31;

    // ---------------- spinner: capacity check + exact fallback ----------------
    if (blockIdx.x == NTILE) {
        if (tid == 0) {
            while (atomicAdd(&g_done, 0) < NTILE) { __nanosleep(200); }
            s_bad = 0;
        }
        __syncthreads();
        const int cap = tc[0] / TOPK;
        if (tid < N_EXP && TOPK * g_count[tid] > cap) atomicOr(&s_bad, 1);
        __syncthreads();
        const int bad = s_bad;
        if (tid < N_EXP) g_count[tid] = 0;    // reset for next replay
        if (tid == 0) g_done = 0;
        if (!bad) return;

        // never-taken exact path: fp32 logits into g_part[0] + serial greedy
        float* gl = g_part;
        for (int p = tid; p < N_TOK * N_EXP; p += 256) {
            const int b = p >> 6, e = p & 63;
            const float4* xr = (const float4*)(x + (size_t)b * DIM);
            const float4* wr = (const float4*)(Wt + (size_t)e * DIM);
            float acc = 0.f;
            for (int i = 0; i < DIM / 4; i++) {
                float4 a = xr[i], cc = wr[i];
                acc = fmaf(a.x, cc.x, acc); acc = fmaf(a.y, cc.y, acc);
                acc = fmaf(a.z, cc.z, acc); acc = fmaf(a.w, cc.w, acc);
            }
            gl[p] = acc + bias[e];
        }
        __syncthreads();
        if (wid == 0) {
            int rem0 = cap, rem1 = cap;
            const float NEG = __int_as_float(0xff800000);
            for (int k = 0; k < TOPK; k++) {
                for (int b = 0; b < N_TOK; b++) {
                    float v0 = gl[(size_t)b * N_EXP + lane];
                    float v1 = gl[(size_t)b * N_EXP + 32 + lane];
                    float om = fmaxf(v0, v1);
                    #pragma unroll
                    for (int o = 16; o > 0; o >>= 1)
                        om = fmaxf(om, __shfl_xor_sync(0xffffffffu, om, o));
                    float os = __expf(v0 - om) + __expf(v1 - om);
                    #pragma unroll
                    for (int o = 16; o > 0; o >>= 1)
                        os += __shfl_xor_sync(0xffffffffu, os, o);
                    float m0v = (rem0 > 0) ? v0 : NEG; int i0 = lane;
                    float m1v = (rem1 > 0) ? v1 : NEG; int i1 = lane + 32;
                    float mv; int mi;
                    if (m1v > m0v) { mv = m1v; mi = i1; } else { mv = m0v; mi = i0; }
                    #pragma unroll
                    for (int o = 16; o > 0; o >>= 1) {
                        float ov = __shfl_xor_sync(0xffffffffu, mv, o);
                        int   oi = __shfl_xor_sync(0xffffffffu, mi, o);
                        if (ov > mv || (ov == mv && oi < mi)) { mv = ov; mi = oi; }
                    }
                    int rsrc = (mi >= 32) ? rem1 : rem0;
                    int remch = __shfl_sync(0xffffffffu, rsrc, mi & 31);
                    bool ok = remch > 0;
                    if (ok && lane == (mi & 31)) { if (mi >= 32) rem1 -= 1; else rem0 -= 1; }
                    if (lane == 0) {
                        if (ok) {
                            float p = __expf(mv - om) / os;
                            out[b * TOPK + k] = (float)mi;
                            out[OUT_W_OFF + b * TOPK + k] = p;
                        } else {
                            out[b * TOPK + k] = -1.f;
                            out[OUT_W_OFF + b * TOPK + k] = 0.f;
                        }
                    }
                    __syncwarp();
                }
            }
            for (int b = lane; b < N_TOK; b += 32) {
                float w0 = out[OUT_W_OFF + b * TOPK + 0];
                float w1 = out[OUT_W_OFF + b * TOPK + 1];
                float w2 = out[OUT_W_OFF + b * TOPK + 2];
                float w3 = out[OUT_W_OFF + b * TOPK + 3];
                float ss = ((w0 + w1) + w2) + w3 + 1e-8f;
                out[OUT_W_OFF + b * TOPK + 0] = w0 / ss;
                out[OUT_W_OFF + b * TOPK + 1] = w1 / ss;
                out[OUT_W_OFF + b * TOPK + 2] = w2 / ss;
                out[OUT_W_OFF + b * TOPK + 3] = w3 / ss;
            }
        }
        return;
    }

    // ---------------- worker blocks: reduce + route 128 tokens ----------------
    const int m0 = blockIdx.x * MT;
    if (tid < N_EXP) { s_bias[tid] = bias[tid]; s_cnt[tid] = 0; }
    if (tid == 0) s_qn = 0;
    __syncthreads();

    // 2 threads per token, each owns 32 experts
    const int t    = tid >> 1;
    const int half = tid & 1;
    const int e0   = half * 32;
    const int b    = m0 + t;

    float v[32];
    {
        const size_t off = (size_t)b * N_EXP + e0;
        const float4* p0 = (const float4*)&g_part[off];
        const float4* p1 = (const float4*)&g_part[(size_t)1 * N_TOK * N_EXP + off];
        const float4* p2 = (const float4*)&g_part[(size_t)2 * N_TOK * N_EXP + off];
        const float4* p3 = (const float4*)&g_part[(size_t)3 * N_TOK * N_EXP + off];
        #pragma unroll
        for (int j = 0; j < 8; j++) {
            float4 a = p0[j], bb = p1[j], cc = p2[j], dd = p3[j];
            v[j*4+0] = ((a.x + bb.x) + cc.x) + dd.x + s_bias[e0 + j*4+0];
            v[j*4+1] = ((a.y + bb.y) + cc.y) + dd.y + s_bias[e0 + j*4+1];
            v[j*4+2] = ((a.z + bb.z) + cc.z) + dd.z + s_bias[e0 + j*4+2];
            v[j*4+3] = ((a.w + bb.w) + cc.w) + dd.w + s_bias[e0 + j*4+3];
        }
    }

    float bm = v[0]; int bi = e0;
    #pragma unroll
    for (int j = 1; j < 32; j++)
        if (v[j] > bm) { bm = v[j]; bi = e0 + j; }

    float om = __shfl_xor_sync(0xffffffffu, bm, 1);
    int   oi = __shfl_xor_sync(0xffffffffu, bi, 1);
    if (om > bm || (om == bm && oi < bi)) { bm = om; bi = oi; }

    const float thr = bm - MARGIN;
    int ncl = 0;
    int cl[4];
    #pragma unroll
    for (int j = 0; j < 32; j++)
        if (v[j] >= thr) { if (ncl < 4) cl[ncl] = e0 + j; ncl++; }
    int nco = __shfl_xor_sync(0xffffffffu, ncl, 1);
    int nc = ncl + nco;
    if (ncl > 4 || nco > 4) nc = 255;       // either half overflowed -> full recompute

    float s = 0.f;
    #pragma unroll
    for (int j = 0; j < 32; j++) s += __expf(v[j] - bm);
    s += __shfl_xor_sync(0xffffffffu, s, 1);

    if (half == 0) {
        const float w = 1.0f / (4.0f + 1e-8f * s);    // p/(4p+1e-8), p = 1/s
        ((float4*)(out + OUT_W_OFF))[b] = make_float4(w, w, w, w);
    }
    if (nc == 1) {
        if (half == 0) {
            float f = (float)bi;
            ((float4*)out)[b] = make_float4(f, f, f, f);
            atomicAdd(&s_cnt[bi], 1);
        }
    } else {
        int base = half ? ((nco <= 4) ? nco : 4) : 0;
        if (nc <= CAND_MAX) {
            for (int i = 0; i < ncl && i < 4; i++) s_cand[t][base + i] = cl[i];
        }
        if (half == 0) {
            s_nc[t] = nc;
            int qi = atomicAdd(&s_qn, 1);
            s_queue[qi] = t;
        }
    }
    __syncthreads();

    // in-block exact fp32 refine for ambiguous tokens (one warp per token)
    {
        const int qn = s_qn;
        for (int q = wid; q < qn; q += 8) {
            const int tt = s_queue[q];
            const int bb = m0 + tt;
            const int nn = s_nc[tt];
            const int it = (nn > CAND_MAX) ? 64 : nn;
            const float4* xr = (const float4*)(x + (size_t)bb * DIM);
            float bestv = -3.4e38f; int besti = 0;
            for (int i = 0; i < it; i++) {
                const int e = (nn > CAND_MAX) ? i : (s_cand[tt][i] & 63);
                const float4* wr = (const float4*)(Wt + (size_t)e * DIM);
                float acc = 0.f;
                #pragma unroll 4
                for (int u = lane; u < DIM / 4; u += 32) {
                    float4 a = xr[u], cc = wr[u];
                    acc = fmaf(a.x, cc.x, acc); acc = fmaf(a.y, cc.y, acc);
                    acc = fmaf(a.z, cc.z, acc); acc = fmaf(a.w, cc.w, acc);
                }
                #pragma unroll
                for (int o = 16; o > 0; o >>= 1) acc += __shfl_xor_sync(0xffffffffu, acc, o);
                acc += s_bias[e];
                if (acc > bestv || (acc == bestv && e < besti)) { bestv = acc; besti = e; }
            }
            if (lane == 0) {
                float f = (float)besti;
                ((float4*)out)[bb] = make_float4(f, f, f, f);
                atomicAdd(&s_cnt[besti], 1);
            }
        }
    }
    __syncthreads();
    if (tid < N_EXP) { int cv = s_cnt[tid]; if (cv) atomicAdd(&g_count[tid], cv); }
    __threadfence();
    __syncthreads();
    if (tid == 0) atomicAdd(&g_done, 1);
}

// ---------------- launch (3 kernels) ----------------
extern "C" void kernel_launch(void* const* d_in, const int* in_sizes, int n_in,
                              void* d_out, int out_size) {
    const float* x    = (const float*)d_in[0];
    const float* W    = (const float*)d_in[1];
    const float* bias = (const float*)d_in[2];
    const int*   tc   = (const int*)  d_in[3];
    float* out = (float*)d_out;

    wconv_kernel<<<N_EXP * DIM / (256 * 8), 256>>>(W);
    gemm_kernel<<<NTILE * NKQ, 256>>>(x);
    route_kernel<<<NTILE + 1, 256>>>(x, W, bias, tc, out);
}